// round 1
// baseline (speedup 1.0000x reference)
#include <cuda_runtime.h>
#include <cstdint>

#define NUM_CODES 100000
#define DIM 64
#define NVISITS 65536
#define LCODES 48

// Pre-scaled tangent table scratch: 100000 * 64 * 4B = 25.6 MB (fits in L2).
__device__ float g_tang[(size_t)NUM_CODES * DIM];

// ---------------------------------------------------------------------------
// Pass 1: tang[c] = (atanh(min(||emb_c||, 1-1e-7)) / max(||emb_c||,1e-15)) * emb_c
// One warp per code row. Each lane owns 2 dims (float2). Butterfly reduce for
// the squared norm, then a Taylor path (data regime: ||x|| ~ 0.008) with an
// accurate atanhf fallback for large norms.
// ---------------------------------------------------------------------------
__global__ void __launch_bounds__(256) build_tangents(const float* __restrict__ emb) {
    int warp = (blockIdx.x * blockDim.x + threadIdx.x) >> 5;
    int lane = threadIdx.x & 31;
    if (warp >= NUM_CODES) return;

    const float2 v = reinterpret_cast<const float2*>(emb + (size_t)warp * DIM)[lane];
    float ss = v.x * v.x + v.y * v.y;
    #pragma unroll
    for (int o = 16; o; o >>= 1)
        ss += __shfl_xor_sync(0xffffffffu, ss, o);

    float s;
    if (ss < 0.09f) {
        // atanh(x)/x = 1 + y/3 + y^2/5 + y^3/7 + y^4/9, y = x^2 = ss.
        // Truncation error < 0.09^5/11 = 5.4e-7 relative.
        s = 1.0f + ss * (0.33333334f + ss * (0.2f + ss * (0.14285715f + ss * 0.11111111f)));
    } else {
        float n = fmaxf(sqrtf(ss), 1e-15f);
        float a = fminf(n, 1.0f - 1e-7f);
        s = atanhf(a) / n;
    }

    float2 t;
    t.x = s * v.x;
    t.y = s * v.y;
    reinterpret_cast<float2*>(g_tang + (size_t)warp * DIM)[lane] = t;
}

// ---------------------------------------------------------------------------
// Pass 2: out[visit] = mean over valid codes of tang[code]. Pure gather+add.
// One warp per visit. Half-warp (16 lanes x float4 = 256B) per code row,
// two codes per iteration -> 24 iterations. Cross-half combine via shfl.
// ---------------------------------------------------------------------------
__global__ void __launch_bounds__(256) visit_mean(const int* __restrict__ ids,
                                                  float* __restrict__ out) {
    int warp = (blockIdx.x * blockDim.x + threadIdx.x) >> 5;
    int lane = threadIdx.x & 31;
    if (warp >= NVISITS) return;

    const int half = lane >> 4;   // 0: even code slots, 1: odd code slots
    const int hl   = lane & 15;   // lane within half -> dims [4*hl, 4*hl+4)

    const int* __restrict__ vid = ids + (size_t)warp * LCODES;

    float4 acc = make_float4(0.f, 0.f, 0.f, 0.f);
    float cnt = 0.f;

    #pragma unroll 8
    for (int t = 0; t < LCODES / 2; t++) {
        int id = __ldg(vid + 2 * t + half);
        if (id >= 0) {
            const float4 v = *reinterpret_cast<const float4*>(
                g_tang + (size_t)id * DIM + hl * 4);
            acc.x += v.x; acc.y += v.y; acc.z += v.z; acc.w += v.w;
            cnt += 1.0f;
        }
    }

    // Combine the two half-warp accumulators (same dims, different code slots).
    acc.x += __shfl_down_sync(0xffffffffu, acc.x, 16);
    acc.y += __shfl_down_sync(0xffffffffu, acc.y, 16);
    acc.z += __shfl_down_sync(0xffffffffu, acc.z, 16);
    acc.w += __shfl_down_sync(0xffffffffu, acc.w, 16);
    cnt   += __shfl_down_sync(0xffffffffu, cnt,   16);

    if (half == 0) {
        float inv = 1.0f / fmaxf(cnt, 1.0f);
        float4 o;
        o.x = acc.x * inv; o.y = acc.y * inv; o.z = acc.z * inv; o.w = acc.w * inv;
        reinterpret_cast<float4*>(out + (size_t)warp * DIM)[hl] = o;
    }
}

extern "C" void kernel_launch(void* const* d_in, const int* in_sizes, int n_in,
                              void* d_out, int out_size) {
    const int*   code_ids = (const int*)d_in[0];   // [N, L] int32, -1 = pad
    const float* emb      = (const float*)d_in[1]; // [NUM_CODES, DIM] fp32
    float*       out      = (float*)d_out;         // [N, DIM] fp32

    (void)in_sizes; (void)n_in; (void)out_size;

    // Pass 1: 100000 warps -> 12500 blocks of 8 warps.
    build_tangents<<<(NUM_CODES + 7) / 8, 256>>>(emb);
    // Pass 2: 65536 warps -> 8192 blocks of 8 warps.
    visit_mean<<<NVISITS / 8, 256>>>(code_ids, out);
}

// round 2
// speedup vs baseline: 1.0530x; 1.0530x over previous
#include <cuda_runtime.h>
#include <cuda_fp16.h>
#include <cstdint>

#define NUM_CODES 100000
#define DIM 64
#define NVISITS 65536
#define LCODES 48

// Pre-scaled tangent table in fp16: 100000 * 64 * 2B = 12.8 MB (L2-resident).
// Row = 64 halfs = 128 B = exactly one L2 line.
__device__ __half2 g_tang[(size_t)NUM_CODES * (DIM / 2)];

// ---------------------------------------------------------------------------
// Pass 1: tang[c] = (atanh(min(||emb_c||,1-1e-7)) / max(||emb_c||,1e-15)) * emb_c
// One warp per code row; lane owns 2 dims. Butterfly norm reduce, Taylor-series
// atanh(x)/x in the small-norm regime (data: ||x|| ~ 0.008), fp16 store.
// ---------------------------------------------------------------------------
__global__ void __launch_bounds__(256) build_tangents(const float* __restrict__ emb) {
    int warp = (blockIdx.x * blockDim.x + threadIdx.x) >> 5;
    int lane = threadIdx.x & 31;
    if (warp >= NUM_CODES) return;

    const float2 v = reinterpret_cast<const float2*>(emb + (size_t)warp * DIM)[lane];
    float ss = v.x * v.x + v.y * v.y;
    #pragma unroll
    for (int o = 16; o; o >>= 1)
        ss += __shfl_xor_sync(0xffffffffu, ss, o);

    float s;
    if (ss < 0.09f) {
        // atanh(x)/x = 1 + y/3 + y^2/5 + y^3/7 + y^4/9, y = x^2 = ss.
        s = 1.0f + ss * (0.33333334f + ss * (0.2f + ss * (0.14285715f + ss * 0.11111111f)));
    } else {
        float n = fmaxf(sqrtf(ss), 1e-15f);
        float a = fminf(n, 1.0f - 1e-7f);
        s = atanhf(a) / n;
    }

    g_tang[(size_t)warp * (DIM / 2) + lane] =
        __float22half2_rn(make_float2(s * v.x, s * v.y));
}

// ---------------------------------------------------------------------------
// Pass 2: out[visit] = mean over valid codes of tang[code].
// One warp per visit. Quarter-warp (8 lanes x 16B = 128B) per fp16 row, so one
// warp-wide LDG.128 gathers FOUR code rows. 48 codes -> 12 iterations.
// Ids are prefetched into 2 registers and distributed via SHFL.IDX.
// fp32 accumulation; cross-quarter combine with shuffles.
// ---------------------------------------------------------------------------
__global__ void __launch_bounds__(256) visit_mean(const int* __restrict__ ids,
                                                  float* __restrict__ out) {
    int warp = (blockIdx.x * blockDim.x + threadIdx.x) >> 5;
    int lane = threadIdx.x & 31;
    if (warp >= NVISITS) return;

    const int quarter = lane >> 3;   // which code slot within the group of 4
    const int ql      = lane & 7;    // lane within quarter -> dims [8*ql, 8*ql+8)

    const int* __restrict__ vid = ids + (size_t)warp * LCODES;

    // Prefetch all 48 ids into two registers per lane.
    const int idA = __ldg(vid + lane);               // slots 0..31
    const int idB = __ldg(vid + 32 + (lane & 15));   // slots 32..47 (dup in hi half)

    float acc[8];
    #pragma unroll
    for (int i = 0; i < 8; i++) acc[i] = 0.f;
    float cnt = 0.f;

    #pragma unroll
    for (int t = 0; t < LCODES / 4; t++) {           // 12 iterations
        int slot = 4 * t + quarter;
        int id = (t < 8) ? __shfl_sync(0xffffffffu, idA, slot)
                         : __shfl_sync(0xffffffffu, idB, slot - 32);
        if (id >= 0) {
            const uint4 raw = *reinterpret_cast<const uint4*>(
                reinterpret_cast<const char*>(g_tang) + (size_t)id * 128 + ql * 16);
            const __half2* h = reinterpret_cast<const __half2*>(&raw);
            #pragma unroll
            for (int j = 0; j < 4; j++) {
                float2 f = __half22float2(h[j]);
                acc[2 * j]     += f.x;
                acc[2 * j + 1] += f.y;
            }
            cnt += 1.0f;
        }
    }

    // Combine the four quarter accumulators (same dims, different code slots).
    #pragma unroll
    for (int o = 16; o >= 8; o >>= 1) {
        #pragma unroll
        for (int i = 0; i < 8; i++)
            acc[i] += __shfl_down_sync(0xffffffffu, acc[i], o);
        cnt += __shfl_down_sync(0xffffffffu, cnt, o);
    }

    if (quarter == 0) {
        float inv = 1.0f / fmaxf(cnt, 1.0f);
        float4 o0 = make_float4(acc[0] * inv, acc[1] * inv, acc[2] * inv, acc[3] * inv);
        float4 o1 = make_float4(acc[4] * inv, acc[5] * inv, acc[6] * inv, acc[7] * inv);
        float4* op = reinterpret_cast<float4*>(out + (size_t)warp * DIM + ql * 8);
        op[0] = o0;
        op[1] = o1;
    }
}

extern "C" void kernel_launch(void* const* d_in, const int* in_sizes, int n_in,
                              void* d_out, int out_size) {
    const int*   code_ids = (const int*)d_in[0];   // [N, L] int32, -1 = pad
    const float* emb      = (const float*)d_in[1]; // [NUM_CODES, DIM] fp32
    float*       out      = (float*)d_out;         // [N, DIM] fp32

    (void)in_sizes; (void)n_in; (void)out_size;

    build_tangents<<<(NUM_CODES + 7) / 8, 256>>>(emb);
    visit_mean<<<NVISITS / 8, 256>>>(code_ids, out);
}